// round 6
// baseline (speedup 1.0000x reference)
#include <cuda_runtime.h>
#include <math.h>

#define NB 16
#define NPT 4096
#define MTOT (NB*NPT)   // 65536 points

__device__ __forceinline__ float gelu_f(float x) {
    return 0.5f * x * (1.0f + tanhf(0.7978845608028654f * (x + 0.044715f * x * x * x)));
}

// ---------------- scratch buffers (device globals; no allocs allowed) ----------------
__device__ float g_c1[NB*16*112*112];      // plane conv1 out
__device__ float g_c2[NB*32*56*56];        // plane conv2 out
__device__ float g_fmap[NB*4*56*56];       // plane conv3 out (fmap)
__device__ float g_ga[NB*4*112*112];       // global enc stages
__device__ float g_gb[NB*8*56*56];
__device__ float g_gcs[NB*16*28*28];
__device__ float g_gd[NB*32*14*14];
__device__ float g_ge[NB*64*7*7];
__device__ float g_gvec[NB*64];            // pooled global code
__device__ float g_gcon[NB*512];           // gc @ W_gc^T per batch
__device__ float g_Wcat[512*512];          // [Wcomb | W_patch]
__device__ float g_biasC[512];             // hb1 + W_pf @ lb2
__device__ float g_embed[MTOT*48];
__device__ float g_feat[(size_t)MTOT*512]; // [h2 | patches]
__device__ float g_hidden[(size_t)MTOT*512];

// ---------------- generic 3x3 conv, pad 1, stride s, gelu ----------------
__global__ void conv3x3_gelu(const float* __restrict__ in, const float* __restrict__ w,
                             const float* __restrict__ bias, float* __restrict__ out,
                             int B, int Cin, int Hin, int Win, int Cout, int Hout, int Wout,
                             int stride) {
    int idx = blockIdx.x * blockDim.x + threadIdx.x;
    int total = B * Cout * Hout * Wout;
    if (idx >= total) return;
    int ox = idx % Wout; int t = idx / Wout;
    int oy = t % Hout;   t /= Hout;
    int co = t % Cout;   int b = t / Cout;
    float acc = bias[co];
    const float* wp = w + co * Cin * 9;
    const float* ip = in + (size_t)b * Cin * Hin * Win;
    int iy0 = oy * stride - 1, ix0 = ox * stride - 1;
    for (int ci = 0; ci < Cin; ci++) {
        const float* ipc = ip + (size_t)ci * Hin * Win;
        const float* wpc = wp + ci * 9;
        #pragma unroll
        for (int ky = 0; ky < 3; ky++) {
            int iy = iy0 + ky;
            if (iy < 0 || iy >= Hin) continue;
            #pragma unroll
            for (int kx = 0; kx < 3; kx++) {
                int ix = ix0 + kx;
                if (ix < 0 || ix >= Win) continue;
                acc += ipc[iy * Win + ix] * wpc[ky * 3 + kx];
            }
        }
    }
    out[idx] = gelu_f(acc);
}

// ---------------- global pooling: mean over 7x7 ----------------
__global__ void gpool_kernel() {
    int idx = blockIdx.x * blockDim.x + threadIdx.x;  // 16*64
    if (idx >= NB * 64) return;
    const float* p = g_ge + idx * 49;
    float s = 0.f;
    #pragma unroll
    for (int i = 0; i < 49; i++) s += p[i];
    g_gvec[idx] = s * (1.0f / 49.0f);
}

// ---------------- per-batch gc contribution: gcon[b,j] = sum_c gc[b,c]*hw1[j,512+c] ----
__global__ void gcon_kernel(const float* __restrict__ hw1) {
    int idx = blockIdx.x * blockDim.x + threadIdx.x;  // 16*512
    if (idx >= NB * 512) return;
    int b = idx >> 9, j = idx & 511;
    float acc = 0.f;
    const float* gv = g_gvec + b * 64;
    const float* hp = hw1 + j * 576 + 512;
    #pragma unroll
    for (int c = 0; c < 64; c++) acc += gv[c] * hp[c];
    g_gcon[idx] = acc;
}

// ---------------- head weight prep: Wcat = [hw1[:,0:256]@lw2 | hw1[:,256:512]] --------
__global__ void prep_head(const float* __restrict__ hw1, const float* __restrict__ hb1,
                          const float* __restrict__ lw2, const float* __restrict__ lb2) {
    int j = blockIdx.x;       // 512
    int t = threadIdx.x;      // 256
    const float* hrow = hw1 + j * 576;
    float acc = 0.f;
    for (int c = 0; c < 256; c++)
        acc += hrow[c] * lw2[c * 256 + t];
    g_Wcat[j * 512 + t] = acc;
    g_Wcat[j * 512 + 256 + t] = hrow[256 + t];
    __shared__ float s[256];
    s[t] = hrow[t] * lb2[t];
    __syncthreads();
    for (int o = 128; o > 0; o >>= 1) {
        if (t < o) s[t] += s[t + o];
        __syncthreads();
    }
    if (t == 0) g_biasC[j] = hb1[j] + s[0];
}

// ---------------- positional embedding ----------------
__global__ void embed_kernel(const float* __restrict__ points) {
    int idx = blockIdx.x * blockDim.x + threadIdx.x;  // MTOT*12
    if (idx >= MTOT * 12) return;
    int m = idx / 12, i = idx % 12;
    float f = (float)(1 << i);
    float px = points[m * 2 + 0], py = points[m * 2 + 1];
    float sx, cx, sy, cy;
    sincosf(f * px, &sx, &cx);
    sincosf(f * py, &sy, &cy);
    float* e = g_embed + m * 48 + 4 * i;
    e[0] = sx; e[1] = sy; e[2] = cx; e[3] = cy;
}

// ---------------- bilinear patch gather into g_feat cols [256,512) -------------------
__global__ void patch_kernel(const float* __restrict__ points) {
    int idx = blockIdx.x * blockDim.x + threadIdx.x;  // MTOT*64
    if (idx >= MTOT * 64) return;
    int pp = idx & 63;
    int m = idx >> 6;
    int i = pp >> 3, j = pp & 7;          // i -> x offset, j -> y offset
    int b = m >> 12;
    float px = points[m * 2 + 0], py = points[m * 2 + 1];
    const float step = 2.0f / 55.0f;
    float gx = (px * 2.0f - 1.0f) + ((float)i - 3.5f) * step;
    float gy = (py * 2.0f - 1.0f) + ((float)j - 3.5f) * step;
    float ix = (gx + 1.0f) * 0.5f * 55.0f;
    float iy = (gy + 1.0f) * 0.5f * 55.0f;
    float x0f = floorf(ix), y0f = floorf(iy);
    int x0 = (int)x0f, y0 = (int)y0f;
    int x1 = x0 + 1, y1 = y0 + 1;
    float wx1 = ix - x0f, wx0 = 1.0f - wx1;
    float wy1 = iy - y0f, wy0 = 1.0f - wy1;
    bool vx0 = (x0 >= 0) & (x0 < 56), vx1 = (x1 >= 0) & (x1 < 56);
    bool vy0 = (y0 >= 0) & (y0 < 56), vy1 = (y1 >= 0) & (y1 < 56);
    int cx0 = min(max(x0, 0), 55), cx1 = min(max(x1, 0), 55);
    int cy0 = min(max(y0, 0), 55), cy1 = min(max(y1, 0), 55);
    float w00 = wx0 * wy0 * ((vx0 && vy0) ? 1.f : 0.f);
    float w10 = wx1 * wy0 * ((vx1 && vy0) ? 1.f : 0.f);
    float w01 = wx0 * wy1 * ((vx0 && vy1) ? 1.f : 0.f);
    float w11 = wx1 * wy1 * ((vx1 && vy1) ? 1.f : 0.f);
    int i00 = cy0 * 56 + cx0, i10 = cy0 * 56 + cx1;
    int i01 = cy1 * 56 + cx0, i11 = cy1 * 56 + cx1;
    const float* fm = g_fmap + (size_t)b * 4 * 3136;
    float* fo = g_feat + (size_t)m * 512 + 256 + pp;
    #pragma unroll
    for (int c = 0; c < 4; c++) {
        const float* base = fm + c * 3136;
        float v = w00 * base[i00] + w10 * base[i10] + w01 * base[i01] + w11 * base[i11];
        fo[c * 64] = v;
    }
}

// ---------------- tiled SGEMM: C[M,N] = gelu(A[M,K] @ W[N,K]^T + bias (+ gcon)) ------
// BM=BN=128, BK=8, 256 threads, 8x8 per thread
__global__ __launch_bounds__(256) void sgemm128(
    const float* __restrict__ A, int lda,
    const float* __restrict__ W, int K,
    float* __restrict__ C, int ldc,
    const float* __restrict__ bias,
    const float* __restrict__ gcon) {
    __shared__ float As[8][128];
    __shared__ float Bs[8][128];
    int tid = threadIdx.x;
    int blockM = blockIdx.y * 128;
    int blockN = blockIdx.x * 128;
    int ty = tid >> 4, tx = tid & 15;
    int arow = tid >> 1;
    int acol = (tid & 1) * 4;
    const float* Aptr = A + (size_t)(blockM + arow) * lda + acol;
    const float* Wptr = W + (size_t)(blockN + arow) * K + acol;

    float acc[8][8];
    #pragma unroll
    for (int i = 0; i < 8; i++)
        #pragma unroll
        for (int j = 0; j < 8; j++) acc[i][j] = 0.f;

    for (int k0 = 0; k0 < K; k0 += 8) {
        float4 av = *reinterpret_cast<const float4*>(Aptr + k0);
        float4 wv = *reinterpret_cast<const float4*>(Wptr + k0);
        As[acol + 0][arow] = av.x; As[acol + 1][arow] = av.y;
        As[acol + 2][arow] = av.z; As[acol + 3][arow] = av.w;
        Bs[acol + 0][arow] = wv.x; Bs[acol + 1][arow] = wv.y;
        Bs[acol + 2][arow] = wv.z; Bs[acol + 3][arow] = wv.w;
        __syncthreads();
        #pragma unroll
        for (int k = 0; k < 8; k++) {
            float a[8], bb[8];
            #pragma unroll
            for (int i = 0; i < 8; i++) a[i] = As[k][ty * 8 + i];
            #pragma unroll
            for (int j = 0; j < 8; j++) bb[j] = Bs[k][tx * 8 + j];
            #pragma unroll
            for (int i = 0; i < 8; i++)
                #pragma unroll
                for (int j = 0; j < 8; j++)
                    acc[i][j] += a[i] * bb[j];
        }
        __syncthreads();
    }
    #pragma unroll
    for (int i = 0; i < 8; i++) {
        int row = blockM + ty * 8 + i;
        const float* grow = gcon ? (gcon + (size_t)(row >> 12) * 512) : nullptr;
        float* crow = C + (size_t)row * ldc;
        #pragma unroll
        for (int j = 0; j < 8; j++) {
            int col = blockN + tx * 8 + j;
            float v = acc[i][j] + bias[col];
            if (grow) v += grow[col];
            crow[col] = gelu_f(v);
        }
    }
}

// ---------------- final dot with hw2 ----------------
__global__ void head_reduce(const float* __restrict__ hw2, const float* __restrict__ hb2,
                            float* __restrict__ out) {
    int m = blockIdx.x * 8 + (threadIdx.x >> 5);
    int lane = threadIdx.x & 31;
    const float* h = g_hidden + (size_t)m * 512;
    float s = 0.f;
    #pragma unroll
    for (int j0 = 0; j0 < 512; j0 += 32)
        s += h[j0 + lane] * hw2[j0 + lane];
    #pragma unroll
    for (int o = 16; o > 0; o >>= 1) s += __shfl_xor_sync(0xFFFFFFFFu, s, o);
    if (lane == 0) out[m] = s + hb2[0];
}

// =====================================================================================
extern "C" void kernel_launch(void* const* d_in, const int* in_sizes, int n_in,
                              void* d_out, int out_size) {
    const float* points = (const float*)d_in[0];
    const float* images = (const float*)d_in[1];
    const float* pw1 = (const float*)d_in[2];  const float* pb1 = (const float*)d_in[3];
    const float* pw2 = (const float*)d_in[4];  const float* pb2 = (const float*)d_in[5];
    const float* pw3 = (const float*)d_in[6];  const float* pb3 = (const float*)d_in[7];
    const float* gw1 = (const float*)d_in[8];  const float* gb1 = (const float*)d_in[9];
    const float* gw2 = (const float*)d_in[10]; const float* gb2 = (const float*)d_in[11];
    const float* gw3 = (const float*)d_in[12]; const float* gb3 = (const float*)d_in[13];
    const float* gw4 = (const float*)d_in[14]; const float* gb4 = (const float*)d_in[15];
    const float* gw5 = (const float*)d_in[16]; const float* gb5 = (const float*)d_in[17];
    const float* lw1 = (const float*)d_in[18]; const float* lb1 = (const float*)d_in[19];
    const float* lw2 = (const float*)d_in[20]; const float* lb2 = (const float*)d_in[21];
    const float* hw1 = (const float*)d_in[22]; const float* hb1 = (const float*)d_in[23];
    const float* hw2 = (const float*)d_in[24]; const float* hb2 = (const float*)d_in[25];
    float* out = (float*)d_out;

    float *c1, *c2, *fmap, *ga, *gb_, *gcs, *gd, *ge, *Wcat, *biasC, *emb, *feat, *hid, *gcon;
    cudaGetSymbolAddress((void**)&c1, g_c1);
    cudaGetSymbolAddress((void**)&c2, g_c2);
    cudaGetSymbolAddress((void**)&fmap, g_fmap);
    cudaGetSymbolAddress((void**)&ga, g_ga);
    cudaGetSymbolAddress((void**)&gb_, g_gb);
    cudaGetSymbolAddress((void**)&gcs, g_gcs);
    cudaGetSymbolAddress((void**)&gd, g_gd);
    cudaGetSymbolAddress((void**)&ge, g_ge);
    cudaGetSymbolAddress((void**)&Wcat, g_Wcat);
    cudaGetSymbolAddress((void**)&biasC, g_biasC);
    cudaGetSymbolAddress((void**)&emb, g_embed);
    cudaGetSymbolAddress((void**)&feat, g_feat);
    cudaGetSymbolAddress((void**)&hid, g_hidden);
    cudaGetSymbolAddress((void**)&gcon, g_gcon);

    const int T = 256;
    auto blocks = [](int n) { return (n + 255) / 256; };

    // ----- plane encoder -----
    conv3x3_gelu<<<blocks(NB*16*112*112), T>>>(images, pw1, pb1, c1, NB, 3, 224, 224, 16, 112, 112, 2);
    conv3x3_gelu<<<blocks(NB*32*56*56),  T>>>(c1, pw2, pb2, c2, NB, 16, 112, 112, 32, 56, 56, 2);
    conv3x3_gelu<<<blocks(NB*4*56*56),   T>>>(c2, pw3, pb3, fmap, NB, 32, 56, 56, 4, 56, 56, 1);

    // ----- global encoder -----
    conv3x3_gelu<<<blocks(NB*4*112*112), T>>>(images, gw1, gb1, ga, NB, 3, 224, 224, 4, 112, 112, 2);
    conv3x3_gelu<<<blocks(NB*8*56*56),   T>>>(ga, gw2, gb2, gb_, NB, 4, 112, 112, 8, 56, 56, 2);
    conv3x3_gelu<<<blocks(NB*16*28*28),  T>>>(gb_, gw3, gb3, gcs, NB, 8, 56, 56, 16, 28, 28, 2);
    conv3x3_gelu<<<blocks(NB*32*14*14),  T>>>(gcs, gw4, gb4, gd, NB, 16, 28, 28, 32, 14, 14, 2);
    conv3x3_gelu<<<blocks(NB*64*7*7),    T>>>(gd, gw5, gb5, ge, NB, 32, 14, 14, 64, 7, 7, 2);
    gpool_kernel<<<blocks(NB*64), T>>>();

    // ----- fold weights / per-batch contributions -----
    prep_head<<<512, 256>>>(hw1, hb1, lw2, lb2);
    gcon_kernel<<<blocks(NB*512), T>>>(hw1);

    // ----- point branch: embed + GEMM1 into feat[:, 0:256] -----
    embed_kernel<<<blocks(MTOT*12), T>>>(points);
    {
        dim3 grid(256 / 128, MTOT / 128);
        sgemm128<<<grid, 256>>>(emb, 48, lw1, 48, feat, 512, lb1, nullptr);
    }

    // ----- patch gather into feat[:, 256:512] -----
    patch_kernel<<<blocks(MTOT*64), T>>>(points);

    // ----- head GEMM: hidden = gelu(feat @ Wcat^T + biasC + gcon[b]) -----
    {
        dim3 grid(512 / 128, MTOT / 128);
        sgemm128<<<grid, 256>>>(feat, 512, Wcat, 512, hid, 512, biasC, gcon);
    }

    // ----- final dot -----
    head_reduce<<<MTOT / 8, 256>>>(hw2, hb2, out);
}

// round 7
// speedup vs baseline: 1.0014x; 1.0014x over previous
#include <cuda_runtime.h>
#include <math.h>

#define NB 16
#define NPT 4096
#define MTOT (NB*NPT)   // 65536 points

__device__ __forceinline__ float gelu_f(float x) {
    return 0.5f * x * (1.0f + tanhf(0.7978845608028654f * (x + 0.044715f * x * x * x)));
}

// ---------------- scratch buffers (device globals; no allocs allowed) ----------------
__device__ float g_c1[NB*16*112*112];      // plane conv1 out
__device__ float g_c2[NB*32*56*56];        // plane conv2 out
__device__ float g_fmap[NB*4*56*56];       // plane conv3 out (fmap)
__device__ float g_ga[NB*4*112*112];       // global enc stages
__device__ float g_gb[NB*8*56*56];
__device__ float g_gcs[NB*16*28*28];
__device__ float g_gd[NB*32*14*14];
__device__ float g_ge[NB*64*7*7];
__device__ float g_gvec[NB*64];            // pooled global code
__device__ float g_gcon[NB*512];           // gc @ W_gc^T per batch
__device__ float g_Wcat[512*512];          // [Wcomb | W_patch]
__device__ float g_biasC[512];             // hb1 + W_pf @ lb2
__device__ float g_embed[MTOT*48];
__device__ float g_feat[(size_t)MTOT*512]; // [h2 | patches]
__device__ float g_hidden[(size_t)MTOT*512];

// ---------------- generic 3x3 conv, pad 1, stride s, gelu ----------------
__global__ void conv3x3_gelu(const float* __restrict__ in, const float* __restrict__ w,
                             const float* __restrict__ bias, float* __restrict__ out,
                             int B, int Cin, int Hin, int Win, int Cout, int Hout, int Wout,
                             int stride) {
    int idx = blockIdx.x * blockDim.x + threadIdx.x;
    int total = B * Cout * Hout * Wout;
    if (idx >= total) return;
    int ox = idx % Wout; int t = idx / Wout;
    int oy = t % Hout;   t /= Hout;
    int co = t % Cout;   int b = t / Cout;
    float acc = bias[co];
    const float* wp = w + co * Cin * 9;
    const float* ip = in + (size_t)b * Cin * Hin * Win;
    int iy0 = oy * stride - 1, ix0 = ox * stride - 1;
    for (int ci = 0; ci < Cin; ci++) {
        const float* ipc = ip + (size_t)ci * Hin * Win;
        const float* wpc = wp + ci * 9;
        #pragma unroll
        for (int ky = 0; ky < 3; ky++) {
            int iy = iy0 + ky;
            if (iy < 0 || iy >= Hin) continue;
            #pragma unroll
            for (int kx = 0; kx < 3; kx++) {
                int ix = ix0 + kx;
                if (ix < 0 || ix >= Win) continue;
                acc += ipc[iy * Win + ix] * wpc[ky * 3 + kx];
            }
        }
    }
    out[idx] = gelu_f(acc);
}

// ---------------- global pooling: mean over 7x7 ----------------
__global__ void gpool_kernel() {
    int idx = blockIdx.x * blockDim.x + threadIdx.x;  // 16*64
    if (idx >= NB * 64) return;
    const float* p = g_ge + idx * 49;
    float s = 0.f;
    #pragma unroll
    for (int i = 0; i < 49; i++) s += p[i];
    g_gvec[idx] = s * (1.0f / 49.0f);
}

// ---------------- per-batch gc contribution: gcon[b,j] = sum_c gc[b,c]*hw1[j,512+c] ----
__global__ void gcon_kernel(const float* __restrict__ hw1) {
    int idx = blockIdx.x * blockDim.x + threadIdx.x;  // 16*512
    if (idx >= NB * 512) return;
    int b = idx >> 9, j = idx & 511;
    float acc = 0.f;
    const float* gv = g_gvec + b * 64;
    const float* hp = hw1 + j * 576 + 512;
    #pragma unroll
    for (int c = 0; c < 64; c++) acc += gv[c] * hp[c];
    g_gcon[idx] = acc;
}

// ---------------- head weight prep: Wcat = [hw1[:,0:256]@lw2 | hw1[:,256:512]] --------
__global__ void prep_head(const float* __restrict__ hw1, const float* __restrict__ hb1,
                          const float* __restrict__ lw2, const float* __restrict__ lb2) {
    int j = blockIdx.x;       // 512
    int t = threadIdx.x;      // 256
    const float* hrow = hw1 + j * 576;
    float acc = 0.f;
    for (int c = 0; c < 256; c++)
        acc += hrow[c] * lw2[c * 256 + t];
    g_Wcat[j * 512 + t] = acc;
    g_Wcat[j * 512 + 256 + t] = hrow[256 + t];
    __shared__ float s[256];
    s[t] = hrow[t] * lb2[t];
    __syncthreads();
    for (int o = 128; o > 0; o >>= 1) {
        if (t < o) s[t] += s[t + o];
        __syncthreads();
    }
    if (t == 0) g_biasC[j] = hb1[j] + s[0];
}

// ---------------- positional embedding ----------------
__global__ void embed_kernel(const float* __restrict__ points) {
    int idx = blockIdx.x * blockDim.x + threadIdx.x;  // MTOT*12
    if (idx >= MTOT * 12) return;
    int m = idx / 12, i = idx % 12;
    float f = (float)(1 << i);
    float px = points[m * 2 + 0], py = points[m * 2 + 1];
    float sx, cx, sy, cy;
    sincosf(f * px, &sx, &cx);
    sincosf(f * py, &sy, &cy);
    float* e = g_embed + m * 48 + 4 * i;
    e[0] = sx; e[1] = sy; e[2] = cx; e[3] = cy;
}

// ---------------- bilinear patch gather into g_feat cols [256,512) -------------------
__global__ void patch_kernel(const float* __restrict__ points) {
    int idx = blockIdx.x * blockDim.x + threadIdx.x;  // MTOT*64
    if (idx >= MTOT * 64) return;
    int pp = idx & 63;
    int m = idx >> 6;
    int i = pp >> 3, j = pp & 7;          // i -> x offset, j -> y offset
    int b = m >> 12;
    float px = points[m * 2 + 0], py = points[m * 2 + 1];
    const float step = 2.0f / 55.0f;
    float gx = (px * 2.0f - 1.0f) + ((float)i - 3.5f) * step;
    float gy = (py * 2.0f - 1.0f) + ((float)j - 3.5f) * step;
    float ix = (gx + 1.0f) * 0.5f * 55.0f;
    float iy = (gy + 1.0f) * 0.5f * 55.0f;
    float x0f = floorf(ix), y0f = floorf(iy);
    int x0 = (int)x0f, y0 = (int)y0f;
    int x1 = x0 + 1, y1 = y0 + 1;
    float wx1 = ix - x0f, wx0 = 1.0f - wx1;
    float wy1 = iy - y0f, wy0 = 1.0f - wy1;
    bool vx0 = (x0 >= 0) & (x0 < 56), vx1 = (x1 >= 0) & (x1 < 56);
    bool vy0 = (y0 >= 0) & (y0 < 56), vy1 = (y1 >= 0) & (y1 < 56);
    int cx0 = min(max(x0, 0), 55), cx1 = min(max(x1, 0), 55);
    int cy0 = min(max(y0, 0), 55), cy1 = min(max(y1, 0), 55);
    float w00 = wx0 * wy0 * ((vx0 && vy0) ? 1.f : 0.f);
    float w10 = wx1 * wy0 * ((vx1 && vy0) ? 1.f : 0.f);
    float w01 = wx0 * wy1 * ((vx0 && vy1) ? 1.f : 0.f);
    float w11 = wx1 * wy1 * ((vx1 && vy1) ? 1.f : 0.f);
    int i00 = cy0 * 56 + cx0, i10 = cy0 * 56 + cx1;
    int i01 = cy1 * 56 + cx0, i11 = cy1 * 56 + cx1;
    const float* fm = g_fmap + (size_t)b * 4 * 3136;
    float* fo = g_feat + (size_t)m * 512 + 256 + pp;
    #pragma unroll
    for (int c = 0; c < 4; c++) {
        const float* base = fm + c * 3136;
        float v = w00 * base[i00] + w10 * base[i10] + w01 * base[i01] + w11 * base[i11];
        fo[c * 64] = v;
    }
}

// ---------------- tiled SGEMM: C[M,N] = gelu(A[M,K] @ W[N,K]^T + bias (+ gcon)) ------
// BM=BN=128, BK=8, 256 threads, 8x8 per thread
__global__ __launch_bounds__(256) void sgemm128(
    const float* __restrict__ A, int lda,
    const float* __restrict__ W, int K,
    float* __restrict__ C, int ldc,
    const float* __restrict__ bias,
    const float* __restrict__ gcon) {
    __shared__ float As[8][128];
    __shared__ float Bs[8][128];
    int tid = threadIdx.x;
    int blockM = blockIdx.y * 128;
    int blockN = blockIdx.x * 128;
    int ty = tid >> 4, tx = tid & 15;
    int arow = tid >> 1;
    int acol = (tid & 1) * 4;
    const float* Aptr = A + (size_t)(blockM + arow) * lda + acol;
    const float* Wptr = W + (size_t)(blockN + arow) * K + acol;

    float acc[8][8];
    #pragma unroll
    for (int i = 0; i < 8; i++)
        #pragma unroll
        for (int j = 0; j < 8; j++) acc[i][j] = 0.f;

    for (int k0 = 0; k0 < K; k0 += 8) {
        float4 av = *reinterpret_cast<const float4*>(Aptr + k0);
        float4 wv = *reinterpret_cast<const float4*>(Wptr + k0);
        As[acol + 0][arow] = av.x; As[acol + 1][arow] = av.y;
        As[acol + 2][arow] = av.z; As[acol + 3][arow] = av.w;
        Bs[acol + 0][arow] = wv.x; Bs[acol + 1][arow] = wv.y;
        Bs[acol + 2][arow] = wv.z; Bs[acol + 3][arow] = wv.w;
        __syncthreads();
        #pragma unroll
        for (int k = 0; k < 8; k++) {
            float a[8], bb[8];
            #pragma unroll
            for (int i = 0; i < 8; i++) a[i] = As[k][ty * 8 + i];
            #pragma unroll
            for (int j = 0; j < 8; j++) bb[j] = Bs[k][tx * 8 + j];
            #pragma unroll
            for (int i = 0; i < 8; i++)
                #pragma unroll
                for (int j = 0; j < 8; j++)
                    acc[i][j] += a[i] * bb[j];
        }
        __syncthreads();
    }
    #pragma unroll
    for (int i = 0; i < 8; i++) {
        int row = blockM + ty * 8 + i;
        const float* grow = gcon ? (gcon + (size_t)(row >> 12) * 512) : nullptr;
        float* crow = C + (size_t)row * ldc;
        #pragma unroll
        for (int j = 0; j < 8; j++) {
            int col = blockN + tx * 8 + j;
            float v = acc[i][j] + bias[col];
            if (grow) v += grow[col];
            crow[col] = gelu_f(v);
        }
    }
}

// ---------------- final dot with hw2 ----------------
__global__ void head_reduce(const float* __restrict__ hw2, const float* __restrict__ hb2,
                            float* __restrict__ out) {
    int m = blockIdx.x * 8 + (threadIdx.x >> 5);
    int lane = threadIdx.x & 31;
    const float* h = g_hidden + (size_t)m * 512;
    float s = 0.f;
    #pragma unroll
    for (int j0 = 0; j0 < 512; j0 += 32)
        s += h[j0 + lane] * hw2[j0 + lane];
    #pragma unroll
    for (int o = 16; o > 0; o >>= 1) s += __shfl_xor_sync(0xFFFFFFFFu, s, o);
    if (lane == 0) out[m] = s + hb2[0];
}

// =====================================================================================
extern "C" void kernel_launch(void* const* d_in, const int* in_sizes, int n_in,
                              void* d_out, int out_size) {
    const float* points = (const float*)d_in[0];
    const float* images = (const float*)d_in[1];
    const float* pw1 = (const float*)d_in[2];  const float* pb1 = (const float*)d_in[3];
    const float* pw2 = (const float*)d_in[4];  const float* pb2 = (const float*)d_in[5];
    const float* pw3 = (const float*)d_in[6];  const float* pb3 = (const float*)d_in[7];
    const float* gw1 = (const float*)d_in[8];  const float* gb1 = (const float*)d_in[9];
    const float* gw2 = (const float*)d_in[10]; const float* gb2 = (const float*)d_in[11];
    const float* gw3 = (const float*)d_in[12]; const float* gb3 = (const float*)d_in[13];
    const float* gw4 = (const float*)d_in[14]; const float* gb4 = (const float*)d_in[15];
    const float* gw5 = (const float*)d_in[16]; const float* gb5 = (const float*)d_in[17];
    const float* lw1 = (const float*)d_in[18]; const float* lb1 = (const float*)d_in[19];
    const float* lw2 = (const float*)d_in[20]; const float* lb2 = (const float*)d_in[21];
    const float* hw1 = (const float*)d_in[22]; const float* hb1 = (const float*)d_in[23];
    const float* hw2 = (const float*)d_in[24]; const float* hb2 = (const float*)d_in[25];
    float* out = (float*)d_out;

    float *c1, *c2, *fmap, *ga, *gb_, *gcs, *gd, *ge, *Wcat, *biasC, *emb, *feat, *hid, *gcon;
    cudaGetSymbolAddress((void**)&c1, g_c1);
    cudaGetSymbolAddress((void**)&c2, g_c2);
    cudaGetSymbolAddress((void**)&fmap, g_fmap);
    cudaGetSymbolAddress((void**)&ga, g_ga);
    cudaGetSymbolAddress((void**)&gb_, g_gb);
    cudaGetSymbolAddress((void**)&gcs, g_gcs);
    cudaGetSymbolAddress((void**)&gd, g_gd);
    cudaGetSymbolAddress((void**)&ge, g_ge);
    cudaGetSymbolAddress((void**)&Wcat, g_Wcat);
    cudaGetSymbolAddress((void**)&biasC, g_biasC);
    cudaGetSymbolAddress((void**)&emb, g_embed);
    cudaGetSymbolAddress((void**)&feat, g_feat);
    cudaGetSymbolAddress((void**)&hid, g_hidden);
    cudaGetSymbolAddress((void**)&gcon, g_gcon);

    const int T = 256;
    auto blocks = [](int n) { return (n + 255) / 256; };

    // ----- plane encoder -----
    conv3x3_gelu<<<blocks(NB*16*112*112), T>>>(images, pw1, pb1, c1, NB, 3, 224, 224, 16, 112, 112, 2);
    conv3x3_gelu<<<blocks(NB*32*56*56),  T>>>(c1, pw2, pb2, c2, NB, 16, 112, 112, 32, 56, 56, 2);
    conv3x3_gelu<<<blocks(NB*4*56*56),   T>>>(c2, pw3, pb3, fmap, NB, 32, 56, 56, 4, 56, 56, 1);

    // ----- global encoder -----
    conv3x3_gelu<<<blocks(NB*4*112*112), T>>>(images, gw1, gb1, ga, NB, 3, 224, 224, 4, 112, 112, 2);
    conv3x3_gelu<<<blocks(NB*8*56*56),   T>>>(ga, gw2, gb2, gb_, NB, 4, 112, 112, 8, 56, 56, 2);
    conv3x3_gelu<<<blocks(NB*16*28*28),  T>>>(gb_, gw3, gb3, gcs, NB, 8, 56, 56, 16, 28, 28, 2);
    conv3x3_gelu<<<blocks(NB*32*14*14),  T>>>(gcs, gw4, gb4, gd, NB, 16, 28, 28, 32, 14, 14, 2);
    conv3x3_gelu<<<blocks(NB*64*7*7),    T>>>(gd, gw5, gb5, ge, NB, 32, 14, 14, 64, 7, 7, 2);
    gpool_kernel<<<blocks(NB*64), T>>>();

    // ----- fold weights / per-batch contributions -----
    prep_head<<<512, 256>>>(hw1, hb1, lw2, lb2);
    gcon_kernel<<<blocks(NB*512), T>>>(hw1);

    // ----- point branch: embed + GEMM1 into feat[:, 0:256] -----
    embed_kernel<<<blocks(MTOT*12), T>>>(points);
    {
        dim3 grid(256 / 128, MTOT / 128);
        sgemm128<<<grid, 256>>>(emb, 48, lw1, 48, feat, 512, lb1, nullptr);
    }

    // ----- patch gather into feat[:, 256:512] -----
    patch_kernel<<<blocks(MTOT*64), T>>>(points);

    // ----- head GEMM: hidden = gelu(feat @ Wcat^T + biasC + gcon[b]) -----
    {
        dim3 grid(512 / 128, MTOT / 128);
        sgemm128<<<grid, 256>>>(feat, 512, Wcat, 512, hid, 512, biasC, gcon);
    }

    // ----- final dot -----
    head_reduce<<<MTOT / 8, 256>>>(hw2, hb2, out);
}

// round 8
// speedup vs baseline: 1.0026x; 1.0012x over previous
#include <cuda_runtime.h>
#include <math.h>

#define NB 16
#define NPT 4096
#define MTOT (NB*NPT)   // 65536 points

__device__ __forceinline__ float gelu_f(float x) {
    return 0.5f * x * (1.0f + tanhf(0.7978845608028654f * (x + 0.044715f * x * x * x)));
}

// ---------------- scratch buffers (device globals; no allocs allowed) ----------------
__device__ float g_c1[NB*16*112*112];      // plane conv1 out
__device__ float g_c2[NB*32*56*56];        // plane conv2 out
__device__ float g_fmap[NB*4*56*56];       // plane conv3 out (fmap)
__device__ float g_ga[NB*4*112*112];       // global enc stages
__device__ float g_gb[NB*8*56*56];
__device__ float g_gcs[NB*16*28*28];
__device__ float g_gd[NB*32*14*14];
__device__ float g_ge[NB*64*7*7];
__device__ float g_gvec[NB*64];            // pooled global code
__device__ float g_gcon[NB*512];           // gc @ W_gc^T per batch
__device__ float g_Wcat[512*512];          // [Wcomb | W_patch]
__device__ float g_biasC[512];             // hb1 + W_pf @ lb2
__device__ float g_embed[MTOT*48];
__device__ float g_feat[(size_t)MTOT*512]; // [h2 | patches]
__device__ float g_hidden[(size_t)MTOT*512];

// ---------------- generic 3x3 conv, pad 1, stride s, gelu ----------------
__global__ void conv3x3_gelu(const float* __restrict__ in, const float* __restrict__ w,
                             const float* __restrict__ bias, float* __restrict__ out,
                             int B, int Cin, int Hin, int Win, int Cout, int Hout, int Wout,
                             int stride) {
    int idx = blockIdx.x * blockDim.x + threadIdx.x;
    int total = B * Cout * Hout * Wout;
    if (idx >= total) return;
    int ox = idx % Wout; int t = idx / Wout;
    int oy = t % Hout;   t /= Hout;
    int co = t % Cout;   int b = t / Cout;
    float acc = bias[co];
    const float* wp = w + co * Cin * 9;
    const float* ip = in + (size_t)b * Cin * Hin * Win;
    int iy0 = oy * stride - 1, ix0 = ox * stride - 1;
    for (int ci = 0; ci < Cin; ci++) {
        const float* ipc = ip + (size_t)ci * Hin * Win;
        const float* wpc = wp + ci * 9;
        #pragma unroll
        for (int ky = 0; ky < 3; ky++) {
            int iy = iy0 + ky;
            if (iy < 0 || iy >= Hin) continue;
            #pragma unroll
            for (int kx = 0; kx < 3; kx++) {
                int ix = ix0 + kx;
                if (ix < 0 || ix >= Win) continue;
                acc += ipc[iy * Win + ix] * wpc[ky * 3 + kx];
            }
        }
    }
    out[idx] = gelu_f(acc);
}

// ---------------- global pooling: mean over 7x7 ----------------
__global__ void gpool_kernel() {
    int idx = blockIdx.x * blockDim.x + threadIdx.x;  // 16*64
    if (idx >= NB * 64) return;
    const float* p = g_ge + idx * 49;
    float s = 0.f;
    #pragma unroll
    for (int i = 0; i < 49; i++) s += p[i];
    g_gvec[idx] = s * (1.0f / 49.0f);
}

// ---------------- per-batch gc contribution: gcon[b,j] = sum_c gc[b,c]*hw1[j,512+c] ----
__global__ void gcon_kernel(const float* __restrict__ hw1) {
    int idx = blockIdx.x * blockDim.x + threadIdx.x;  // 16*512
    if (idx >= NB * 512) return;
    int b = idx >> 9, j = idx & 511;
    float acc = 0.f;
    const float* gv = g_gvec + b * 64;
    const float* hp = hw1 + j * 576 + 512;
    #pragma unroll
    for (int c = 0; c < 64; c++) acc += gv[c] * hp[c];
    g_gcon[idx] = acc;
}

// ---------------- head weight prep: Wcat = [hw1[:,0:256]@lw2 | hw1[:,256:512]] --------
__global__ void prep_head(const float* __restrict__ hw1, const float* __restrict__ hb1,
                          const float* __restrict__ lw2, const float* __restrict__ lb2) {
    int j = blockIdx.x;       // 512
    int t = threadIdx.x;      // 256
    const float* hrow = hw1 + j * 576;
    float acc = 0.f;
    for (int c = 0; c < 256; c++)
        acc += hrow[c] * lw2[c * 256 + t];
    g_Wcat[j * 512 + t] = acc;
    g_Wcat[j * 512 + 256 + t] = hrow[256 + t];
    __shared__ float s[256];
    s[t] = hrow[t] * lb2[t];
    __syncthreads();
    for (int o = 128; o > 0; o >>= 1) {
        if (t < o) s[t] += s[t + o];
        __syncthreads();
    }
    if (t == 0) g_biasC[j] = hb1[j] + s[0];
}

// ---------------- positional embedding ----------------
__global__ void embed_kernel(const float* __restrict__ points) {
    int idx = blockIdx.x * blockDim.x + threadIdx.x;  // MTOT*12
    if (idx >= MTOT * 12) return;
    int m = idx / 12, i = idx % 12;
    float f = (float)(1 << i);
    float px = points[m * 2 + 0], py = points[m * 2 + 1];
    float sx, cx, sy, cy;
    sincosf(f * px, &sx, &cx);
    sincosf(f * py, &sy, &cy);
    float* e = g_embed + m * 48 + 4 * i;
    e[0] = sx; e[1] = sy; e[2] = cx; e[3] = cy;
}

// ---------------- bilinear patch gather into g_feat cols [256,512) -------------------
__global__ void patch_kernel(const float* __restrict__ points) {
    int idx = blockIdx.x * blockDim.x + threadIdx.x;  // MTOT*64
    if (idx >= MTOT * 64) return;
    int pp = idx & 63;
    int m = idx >> 6;
    int i = pp >> 3, j = pp & 7;          // i -> x offset, j -> y offset
    int b = m >> 12;
    float px = points[m * 2 + 0], py = points[m * 2 + 1];
    const float step = 2.0f / 55.0f;
    float gx = (px * 2.0f - 1.0f) + ((float)i - 3.5f) * step;
    float gy = (py * 2.0f - 1.0f) + ((float)j - 3.5f) * step;
    float ix = (gx + 1.0f) * 0.5f * 55.0f;
    float iy = (gy + 1.0f) * 0.5f * 55.0f;
    float x0f = floorf(ix), y0f = floorf(iy);
    int x0 = (int)x0f, y0 = (int)y0f;
    int x1 = x0 + 1, y1 = y0 + 1;
    float wx1 = ix - x0f, wx0 = 1.0f - wx1;
    float wy1 = iy - y0f, wy0 = 1.0f - wy1;
    bool vx0 = (x0 >= 0) & (x0 < 56), vx1 = (x1 >= 0) & (x1 < 56);
    bool vy0 = (y0 >= 0) & (y0 < 56), vy1 = (y1 >= 0) & (y1 < 56);
    int cx0 = min(max(x0, 0), 55), cx1 = min(max(x1, 0), 55);
    int cy0 = min(max(y0, 0), 55), cy1 = min(max(y1, 0), 55);
    float w00 = wx0 * wy0 * ((vx0 && vy0) ? 1.f : 0.f);
    float w10 = wx1 * wy0 * ((vx1 && vy0) ? 1.f : 0.f);
    float w01 = wx0 * wy1 * ((vx0 && vy1) ? 1.f : 0.f);
    float w11 = wx1 * wy1 * ((vx1 && vy1) ? 1.f : 0.f);
    int i00 = cy0 * 56 + cx0, i10 = cy0 * 56 + cx1;
    int i01 = cy1 * 56 + cx0, i11 = cy1 * 56 + cx1;
    const float* fm = g_fmap + (size_t)b * 4 * 3136;
    float* fo = g_feat + (size_t)m * 512 + 256 + pp;
    #pragma unroll
    for (int c = 0; c < 4; c++) {
        const float* base = fm + c * 3136;
        float v = w00 * base[i00] + w10 * base[i10] + w01 * base[i01] + w11 * base[i11];
        fo[c * 64] = v;
    }
}

// ---------------- tiled SGEMM: C[M,N] = gelu(A[M,K] @ W[N,K]^T + bias (+ gcon)) ------
// BM=BN=128, BK=8, 256 threads, 8x8 per thread
__global__ __launch_bounds__(256) void sgemm128(
    const float* __restrict__ A, int lda,
    const float* __restrict__ W, int K,
    float* __restrict__ C, int ldc,
    const float* __restrict__ bias,
    const float* __restrict__ gcon) {
    __shared__ float As[8][128];
    __shared__ float Bs[8][128];
    int tid = threadIdx.x;
    int blockM = blockIdx.y * 128;
    int blockN = blockIdx.x * 128;
    int ty = tid >> 4, tx = tid & 15;
    int arow = tid >> 1;
    int acol = (tid & 1) * 4;
    const float* Aptr = A + (size_t)(blockM + arow) * lda + acol;
    const float* Wptr = W + (size_t)(blockN + arow) * K + acol;

    float acc[8][8];
    #pragma unroll
    for (int i = 0; i < 8; i++)
        #pragma unroll
        for (int j = 0; j < 8; j++) acc[i][j] = 0.f;

    for (int k0 = 0; k0 < K; k0 += 8) {
        float4 av = *reinterpret_cast<const float4*>(Aptr + k0);
        float4 wv = *reinterpret_cast<const float4*>(Wptr + k0);
        As[acol + 0][arow] = av.x; As[acol + 1][arow] = av.y;
        As[acol + 2][arow] = av.z; As[acol + 3][arow] = av.w;
        Bs[acol + 0][arow] = wv.x; Bs[acol + 1][arow] = wv.y;
        Bs[acol + 2][arow] = wv.z; Bs[acol + 3][arow] = wv.w;
        __syncthreads();
        #pragma unroll
        for (int k = 0; k < 8; k++) {
            float a[8], bb[8];
            #pragma unroll
            for (int i = 0; i < 8; i++) a[i] = As[k][ty * 8 + i];
            #pragma unroll
            for (int j = 0; j < 8; j++) bb[j] = Bs[k][tx * 8 + j];
            #pragma unroll
            for (int i = 0; i < 8; i++)
                #pragma unroll
                for (int j = 0; j < 8; j++)
                    acc[i][j] += a[i] * bb[j];
        }
        __syncthreads();
    }
    #pragma unroll
    for (int i = 0; i < 8; i++) {
        int row = blockM + ty * 8 + i;
        const float* grow = gcon ? (gcon + (size_t)(row >> 12) * 512) : nullptr;
        float* crow = C + (size_t)row * ldc;
        #pragma unroll
        for (int j = 0; j < 8; j++) {
            int col = blockN + tx * 8 + j;
            float v = acc[i][j] + bias[col];
            if (grow) v += grow[col];
            crow[col] = gelu_f(v);
        }
    }
}

// ---------------- final dot with hw2 ----------------
__global__ void head_reduce(const float* __restrict__ hw2, const float* __restrict__ hb2,
                            float* __restrict__ out) {
    int m = blockIdx.x * 8 + (threadIdx.x >> 5);
    int lane = threadIdx.x & 31;
    const float* h = g_hidden + (size_t)m * 512;
    float s = 0.f;
    #pragma unroll
    for (int j0 = 0; j0 < 512; j0 += 32)
        s += h[j0 + lane] * hw2[j0 + lane];
    #pragma unroll
    for (int o = 16; o > 0; o >>= 1) s += __shfl_xor_sync(0xFFFFFFFFu, s, o);
    if (lane == 0) out[m] = s + hb2[0];
}

// =====================================================================================
extern "C" void kernel_launch(void* const* d_in, const int* in_sizes, int n_in,
                              void* d_out, int out_size) {
    const float* points = (const float*)d_in[0];
    const float* images = (const float*)d_in[1];
    const float* pw1 = (const float*)d_in[2];  const float* pb1 = (const float*)d_in[3];
    const float* pw2 = (const float*)d_in[4];  const float* pb2 = (const float*)d_in[5];
    const float* pw3 = (const float*)d_in[6];  const float* pb3 = (const float*)d_in[7];
    const float* gw1 = (const float*)d_in[8];  const float* gb1 = (const float*)d_in[9];
    const float* gw2 = (const float*)d_in[10]; const float* gb2 = (const float*)d_in[11];
    const float* gw3 = (const float*)d_in[12]; const float* gb3 = (const float*)d_in[13];
    const float* gw4 = (const float*)d_in[14]; const float* gb4 = (const float*)d_in[15];
    const float* gw5 = (const float*)d_in[16]; const float* gb5 = (const float*)d_in[17];
    const float* lw1 = (const float*)d_in[18]; const float* lb1 = (const float*)d_in[19];
    const float* lw2 = (const float*)d_in[20]; const float* lb2 = (const float*)d_in[21];
    const float* hw1 = (const float*)d_in[22]; const float* hb1 = (const float*)d_in[23];
    const float* hw2 = (const float*)d_in[24]; const float* hb2 = (const float*)d_in[25];
    float* out = (float*)d_out;

    float *c1, *c2, *fmap, *ga, *gb_, *gcs, *gd, *ge, *Wcat, *biasC, *emb, *feat, *hid, *gcon;
    cudaGetSymbolAddress((void**)&c1, g_c1);
    cudaGetSymbolAddress((void**)&c2, g_c2);
    cudaGetSymbolAddress((void**)&fmap, g_fmap);
    cudaGetSymbolAddress((void**)&ga, g_ga);
    cudaGetSymbolAddress((void**)&gb_, g_gb);
    cudaGetSymbolAddress((void**)&gcs, g_gcs);
    cudaGetSymbolAddress((void**)&gd, g_gd);
    cudaGetSymbolAddress((void**)&ge, g_ge);
    cudaGetSymbolAddress((void**)&Wcat, g_Wcat);
    cudaGetSymbolAddress((void**)&biasC, g_biasC);
    cudaGetSymbolAddress((void**)&emb, g_embed);
    cudaGetSymbolAddress((void**)&feat, g_feat);
    cudaGetSymbolAddress((void**)&hid, g_hidden);
    cudaGetSymbolAddress((void**)&gcon, g_gcon);

    const int T = 256;
    auto blocks = [](int n) { return (n + 255) / 256; };

    // ----- plane encoder -----
    conv3x3_gelu<<<blocks(NB*16*112*112), T>>>(images, pw1, pb1, c1, NB, 3, 224, 224, 16, 112, 112, 2);
    conv3x3_gelu<<<blocks(NB*32*56*56),  T>>>(c1, pw2, pb2, c2, NB, 16, 112, 112, 32, 56, 56, 2);
    conv3x3_gelu<<<blocks(NB*4*56*56),   T>>>(c2, pw3, pb3, fmap, NB, 32, 56, 56, 4, 56, 56, 1);

    // ----- global encoder -----
    conv3x3_gelu<<<blocks(NB*4*112*112), T>>>(images, gw1, gb1, ga, NB, 3, 224, 224, 4, 112, 112, 2);
    conv3x3_gelu<<<blocks(NB*8*56*56),   T>>>(ga, gw2, gb2, gb_, NB, 4, 112, 112, 8, 56, 56, 2);
    conv3x3_gelu<<<blocks(NB*16*28*28),  T>>>(gb_, gw3, gb3, gcs, NB, 8, 56, 56, 16, 28, 28, 2);
    conv3x3_gelu<<<blocks(NB*32*14*14),  T>>>(gcs, gw4, gb4, gd, NB, 16, 28, 28, 32, 14, 14, 2);
    conv3x3_gelu<<<blocks(NB*64*7*7),    T>>>(gd, gw5, gb5, ge, NB, 32, 14, 14, 64, 7, 7, 2);
    gpool_kernel<<<blocks(NB*64), T>>>();

    // ----- fold weights / per-batch contributions -----
    prep_head<<<512, 256>>>(hw1, hb1, lw2, lb2);
    gcon_kernel<<<blocks(NB*512), T>>>(hw1);

    // ----- point branch: embed + GEMM1 into feat[:, 0:256] -----
    embed_kernel<<<blocks(MTOT*12), T>>>(points);
    {
        dim3 grid(256 / 128, MTOT / 128);
        sgemm128<<<grid, 256>>>(emb, 48, lw1, 48, feat, 512, lb1, nullptr);
    }

    // ----- patch gather into feat[:, 256:512] -----
    patch_kernel<<<blocks(MTOT*64), T>>>(points);

    // ----- head GEMM: hidden = gelu(feat @ Wcat^T + biasC + gcon[b]) -----
    {
        dim3 grid(512 / 128, MTOT / 128);
        sgemm128<<<grid, 256>>>(feat, 512, Wcat, 512, hid, 512, biasC, gcon);
    }

    // ----- final dot -----
    head_reduce<<<MTOT / 8, 256>>>(hw2, hb2, out);
}